// round 10
// baseline (speedup 1.0000x reference)
#include <cuda_runtime.h>
#include <cuda_fp16.h>
#include <stdint.h>
#include <math.h>

#define NSAMP 64
#define NBLOCKS 10000          // 1 ray per block, M = 64 sample-rows
#define FXc 86.6f
#define NEAR_ 2.0f
#define FAR_ 6.0f
#define DINF 1e10f

// ---------------- global scratch (weights as fp16, [N][K]) ----------------
__device__ float g_z[NSAMP];
__device__ float g_dists[NSAMP];
__device__ float g_sig_last[10000];
__device__ __align__(16) __half g_w1T[256 * 64];
__device__ __align__(16) __half g_w2T[256 * 256];
__device__ __align__(16) __half g_wdT[128 * 256];

// ---------------- smem layout (bytes) ----------------
// [0, 8192)       misc floats
// [8192, 41984)   A plane: 64 rows x 264 fp16 (row stride 528 B)
// [41984, 103424) B stages: 3 x 20480 B (256 rows x 40 fp16, 80 B stride)
#define A_OFF     8192u
#define B_OFF     41984u
#define STAGE_B   20480u
#define BROW      80u
#define AROW      528u
#define SMEM_BYTES 103424      // x2 CTAs = 206848 <= 227KB

// misc float offsets (1 ray)
#define F_RAY   0      // 12: o(3) d(3) v(3) norm
#define F_B1    32
#define F_B2    288
#define F_WSIG  544
#define F_WRGB  800    // 384
#define F_EDIR  1184   // 32
#define F_DC    1216   // 128
#define F_SIGP  1344   // [2][64] sigma partials; later alpha in [0..63]
#define F_RGB   1472   // [64][3]
#define F_RGBP  1664   // [2][192]

// ---------------- asm helpers ----------------
__device__ __forceinline__ uint32_t smem_u32(const void* p) {
    uint32_t a;
    asm("{ .reg .u64 t; cvta.to.shared.u64 t, %1; cvt.u32.u64 %0, t; }" : "=r"(a) : "l"(p));
    return a;
}
__device__ __forceinline__ uint32_t lds32(uint32_t a) {
    uint32_t v; asm volatile("ld.shared.b32 %0, [%1];" : "=r"(v) : "r"(a)); return v;
}
__device__ __forceinline__ void sts32(uint32_t a, uint32_t v) {
    asm volatile("st.shared.b32 [%0], %1;" :: "r"(a), "r"(v));
}
__device__ __forceinline__ void mma_f16(float* c, const uint32_t* a, uint32_t b0, uint32_t b1) {
    asm volatile(
        "mma.sync.aligned.m16n8k16.row.col.f32.f16.f16.f32 "
        "{%0,%1,%2,%3}, {%4,%5,%6,%7}, {%8,%9}, {%0,%1,%2,%3};"
        : "+f"(c[0]), "+f"(c[1]), "+f"(c[2]), "+f"(c[3])
        : "r"(a[0]), "r"(a[1]), "r"(a[2]), "r"(a[3]), "r"(b0), "r"(b1));
}
__device__ __forceinline__ void cpa16(uint32_t d, const void* s) {
    asm volatile("cp.async.ca.shared.global [%0], [%1], 16;" :: "r"(d), "l"(s));
}
#define CP_COMMIT() asm volatile("cp.async.commit_group;" ::: "memory")
#define CP_WAIT1()  asm volatile("cp.async.wait_group 1;" ::: "memory")

__device__ __forceinline__ uint32_t pack_h2(float a, float b) {
    __half2 h = __floats2half2_rn(a, b);
    return *reinterpret_cast<uint32_t*>(&h);
}
__device__ __forceinline__ float qred(float v) {
    v += __shfl_xor_sync(0xffffffffu, v, 1);
    v += __shfl_xor_sync(0xffffffffu, v, 2);
    return v;
}

// schedule: 18 K32 items = G1 x2, G2 x8, G3 x8
__device__ __forceinline__ void fill_item(int t, uint32_t bB, int tid) {
    if (t >= 18) return;
    const __half* src; int nrows, kst, kb;
    if (t < 2)       { src = g_w1T; nrows = 256; kst = 64;  kb = t * 32; }
    else if (t < 10) { src = g_w2T; nrows = 256; kst = 256; kb = (t - 2) * 32; }
    else             { src = g_wdT; nrows = 128; kst = 256; kb = (t - 10) * 32; }
    uint32_t dst = bB + (uint32_t)(t % 3) * STAGE_B;
    for (int i = tid; i < nrows * 4; i += 256) {
        int n = i >> 2, seg = i & 3;
        cpa16(dst + (uint32_t)n * BROW + (uint32_t)seg * 16u,
              src + n * kst + kb + seg * 8);
    }
}

// GEMM: M=64 (4 M-warp-groups x 16 rows), 2 N-warp-groups, K=32 per chunk.
// 3-stage ring, ONE barrier per chunk.
template<int NT>
__device__ __forceinline__ void gemm_run(float (*C)[4], int nchunks,
                                         uint32_t aP, uint32_t bB, uint32_t nbase,
                                         int tid, int lane, int r0, int& t) {
    const uint32_t arow = (uint32_t)r0 * AROW + (uint32_t)(lane & 3) * 4u;
    const uint32_t brow = nbase + (uint32_t)(lane >> 2) * BROW + (uint32_t)(lane & 3) * 4u;
    #pragma unroll
    for (int i = 0; i < NT; i++) { C[i][0] = 0.f; C[i][1] = 0.f; C[i][2] = 0.f; C[i][3] = 0.f; }
    #pragma unroll 1
    for (int ch = 0; ch < nchunks; ch++) {
        CP_WAIT1();
        __syncthreads();
        uint32_t bs = bB + (uint32_t)(t % 3) * STAGE_B;
        #pragma unroll
        for (int k16 = 0; k16 < 2; k16++) {
            uint32_t kb = (uint32_t)(ch * 64 + k16 * 32);
            uint32_t ah = aP + arow + kb;
            uint32_t a[4];
            a[0] = lds32(ah);        a[1] = lds32(ah + 8 * AROW);
            a[2] = lds32(ah + 16);   a[3] = lds32(ah + 8 * AROW + 16);
            uint32_t bk = bs + brow + (uint32_t)k16 * 32u;
            #pragma unroll
            for (int nt = 0; nt < NT; nt++) {
                uint32_t ba = bk + (uint32_t)nt * (8u * BROW);
                mma_f16(C[nt], a, lds32(ba), lds32(ba + 16));
            }
        }
        fill_item(t + 2, bB, tid);
        CP_COMMIT();
        t++;
    }
}

// ---------------- aux kernels ----------------
__global__ void precompute_kernel(const float* __restrict__ t_rand) {
    __shared__ float zsh[NSAMP];
    int i = threadIdx.x;
    float t   = (float)i / 63.0f;
    float z0  = NEAR_ * (1.0f - t) + FAR_ * t;
    float tn  = (float)(i + 1) / 63.0f;
    float z0n = NEAR_ * (1.0f - tn) + FAR_ * tn;
    float tp  = (float)(i - 1) / 63.0f;
    float z0p = NEAR_ * (1.0f - tp) + FAR_ * tp;
    float upper = (i < NSAMP - 1) ? 0.5f * (z0 + z0n) : z0;
    float lower = (i > 0) ? 0.5f * (z0p + z0) : z0;
    float z = lower + (upper - lower) * t_rand[i];
    zsh[i] = z;
    g_z[i] = z;
    __syncthreads();
    g_dists[i] = (i < NSAMP - 1) ? (zsh[i + 1] - zsh[i]) : DINF;
}

__global__ void prep_weights(const float* __restrict__ w1,
                             const float* __restrict__ w2,
                             const float* __restrict__ wd) {
    int idx = blockIdx.x * 256 + threadIdx.x;
    if (idx < 16384) {
        int n = idx >> 6, k = idx & 63;
        g_w1T[idx] = __float2half((k < 63) ? w1[k * 256 + n] : 0.0f);
    } else if (idx < 16384 + 65536) {
        int t = idx - 16384; int n = t >> 8, k = t & 255;
        g_w2T[t] = __float2half(w2[k * 256 + n]);
    } else if (idx < 16384 + 65536 + 32768) {
        int t = idx - 16384 - 65536; int n = t >> 8, k = t & 255;
        g_wdT[t] = __float2half(wd[k * 128 + n]);
    }
}

// exact fp32 sigma for the LAST sample of each ray (alpha there is a step fn of sign(sigma))
__global__ void __launch_bounds__(256) sigma_exact(
    const float* __restrict__ c2w,
    const float* __restrict__ w1g, const float* __restrict__ b1g,
    const float* __restrict__ w2g, const float* __restrict__ b2g,
    const float* __restrict__ wsigg, const float* __restrict__ bsigg)
{
    __shared__ float enc[16][64];
    __shared__ float h1s[16][260];
    __shared__ float red[16][8];
    int tid = threadIdx.x;
    int r = tid >> 4, sub = tid & 15;
    {
        int ray = blockIdx.x * 16 + r;
        int cx = ray % 100, rw = ray / 100;
        float dx = ((float)cx - 50.0f) / FXc;
        float dy = -(((float)rw - 50.0f) / FXc);
        float d0 = dx * c2w[0] + dy * c2w[1] - c2w[2];
        float d1 = dx * c2w[4] + dy * c2w[5] - c2w[6];
        float d2 = dx * c2w[8] + dy * c2w[9] - c2w[10];
        float z = g_z[63];
        float pt[3];
        pt[0] = fmaf(d0, z, c2w[3]);
        pt[1] = fmaf(d1, z, c2w[7]);
        pt[2] = fmaf(d2, z, c2w[11]);
        #pragma unroll
        for (int q = 0; q < 4; q++) {
            int dd = sub * 4 + q;
            float val = 0.f;
            if (dd < 3) val = pt[dd];
            else if (dd < 63) {
                int u = dd - 3, l = u / 6, r6 = u % 6, cc = r6 % 3;
                float x = pt[cc] * (float)(1 << l);
                val = (r6 < 3) ? sinf(x) : cosf(x);
            }
            enc[r][dd] = val;
        }
    }
    __syncthreads();
    float acc[16];
    {
        float b = b1g[tid];
        #pragma unroll
        for (int i = 0; i < 16; i++) acc[i] = b;
        #pragma unroll 1
        for (int k = 0; k < 63; k++) {
            float w = w1g[k * 256 + tid];
            #pragma unroll
            for (int i = 0; i < 16; i++) acc[i] = fmaf(enc[i][k], w, acc[i]);
        }
        #pragma unroll
        for (int i = 0; i < 16; i++) h1s[i][tid] = fmaxf(acc[i], 0.f);
    }
    __syncthreads();
    {
        float b = b2g[tid];
        #pragma unroll
        for (int i = 0; i < 16; i++) acc[i] = b;
        #pragma unroll 1
        for (int k = 0; k < 256; k++) {
            float w = w2g[k * 256 + tid];
            #pragma unroll
            for (int i = 0; i < 16; i++) acc[i] = fmaf(h1s[i][k], w, acc[i]);
        }
    }
    {
        float ws = wsigg[tid];
        #pragma unroll
        for (int i = 0; i < 16; i++) {
            float v = fmaxf(acc[i], 0.f) * ws;
            v += __shfl_xor_sync(0xffffffffu, v, 16);
            v += __shfl_xor_sync(0xffffffffu, v, 8);
            v += __shfl_xor_sync(0xffffffffu, v, 4);
            v += __shfl_xor_sync(0xffffffffu, v, 2);
            v += __shfl_xor_sync(0xffffffffu, v, 1);
            if ((tid & 31) == 0) red[i][tid >> 5] = v;
        }
        __syncthreads();
        if (tid < 16) {
            float s = bsigg[0];
            #pragma unroll
            for (int w = 0; w < 8; w++) s += red[tid][w];
            g_sig_last[blockIdx.x * 16 + tid] = s;
        }
    }
}

// ---------------- main fused kernel (256 threads, 2 CTAs/SM) ----------------
__global__ void __launch_bounds__(256, 2) nerf_v3(
    const float* __restrict__ c2w,
    const float* __restrict__ b1g,  const float* __restrict__ b2g,
    const float* __restrict__ wsigg,const float* __restrict__ bsigg,
    const float* __restrict__ wdirg,const float* __restrict__ bdirg,
    const float* __restrict__ wrgbg,const float* __restrict__ brgbg,
    float* __restrict__ out)
{
    extern __shared__ char smraw[];
    float* smf = (float*)smraw;
    const uint32_t base = smem_u32(smraw);
    const uint32_t aP = base + A_OFF, bB = base + B_OFF;
    const int tid = threadIdx.x, lane = tid & 31, wid = tid >> 5;
    const int wn = wid & 1, wm = wid >> 1;        // 2 N-halves x 4 M-groups
    const int r0 = wm * 16 + (lane >> 2);         // rows 0..63 (with +8 sibling)
    const int ray = blockIdx.x;
    int t = 0;

    // prefetch first two chunk items
    fill_item(0, bB, tid); CP_COMMIT();
    fill_item(1, bB, tid); CP_COMMIT();

    // stage small tensors
    {
        smf[F_B1 + tid]   = b1g[tid];
        smf[F_B2 + tid]   = b2g[tid];
        smf[F_WSIG + tid] = wsigg[tid];
        smf[F_WRGB + tid] = wrgbg[tid];
        if (tid < 128) smf[F_WRGB + 256 + tid] = wrgbg[256 + tid];
    }
    if (tid == 0) {
        int c = ray % 100, rw = ray / 100;
        float dx = ((float)c - 50.0f) / FXc;
        float dy = -(((float)rw - 50.0f) / FXc);
        float d0 = dx * c2w[0] + dy * c2w[1] - c2w[2];
        float d1 = dx * c2w[4] + dy * c2w[5] - c2w[6];
        float d2 = dx * c2w[8] + dy * c2w[9] - c2w[10];
        float nrm = sqrtf(d0 * d0 + d1 * d1 + d2 * d2);
        float* R = smf + F_RAY;
        R[0] = c2w[3]; R[1] = c2w[7]; R[2] = c2w[11];
        R[3] = d0; R[4] = d1; R[5] = d2;
        R[6] = d0 / nrm; R[7] = d1 / nrm; R[8] = d2 / nrm;
        R[9] = nrm;
    }
    __syncthreads();

    // enc_dir (27) — precise (feeds fp32 dc path)
    if (tid < 27) {
        const float* vv = smf + F_RAY + 6;
        float val;
        if (tid < 3) val = vv[tid];
        else {
            int u = tid - 3, l = u / 6, r6 = u % 6, cc = r6 % 3;
            float x = vv[cc] * (float)(1 << l);
            val = (r6 < 3) ? sinf(x) : cosf(x);
        }
        smf[F_EDIR + tid] = val;
    }
    __syncthreads();

    // dir-head rank-1 bias dc[128] (fp32)
    if (tid < 128) {
        float acc = bdirg[tid];
        #pragma unroll
        for (int dd = 0; dd < 27; dd++)
            acc = fmaf(smf[F_EDIR + dd], wdirg[(256 + dd) * 128 + tid], acc);
        smf[F_DC + tid] = acc;
    }

    // posenc(pts) -> A plane fp16; fast sin/cos (error << fp16 rounding budget)
    if (tid < 64) {
        float z = g_z[tid];
        const float* R = smf + F_RAY;
        float v[64];
        float f0 = fmaf(R[3], z, R[0]);
        float f1 = fmaf(R[4], z, R[1]);
        float f2 = fmaf(R[5], z, R[2]);
        v[0] = f0; v[1] = f1; v[2] = f2;
        #pragma unroll
        for (int l = 0; l < 10; l++) {
            int b = 3 + l * 6;
            v[b]     = __sinf(f0); v[b + 1] = __sinf(f1); v[b + 2] = __sinf(f2);
            v[b + 3] = __cosf(f0); v[b + 4] = __cosf(f1); v[b + 5] = __cosf(f2);
            f0 *= 2.0f; f1 *= 2.0f; f2 *= 2.0f;
        }
        v[63] = 0.0f;
        uint32_t pk[32];
        #pragma unroll
        for (int i = 0; i < 32; i++) pk[i] = pack_h2(v[2 * i], v[2 * i + 1]);
        char* p = smraw + A_OFF + (uint32_t)tid * AROW;
        #pragma unroll
        for (int q = 0; q < 8; q++)
            *(uint4*)(p + q * 16) = ((uint4*)pk)[q];
    }
    // (gemm_run's first barrier orders A writes vs reads)

    float C[16][4];

    // ---------------- GEMM1: h1 = relu(enc @ w1 + b1), N=256, K=64 ----------------
    gemm_run<16>(C, 2, aP, bB, (uint32_t)wn * 128u * BROW, tid, lane, r0, t);
    __syncthreads();
    {   // ep1: bias+relu -> A plane (fp16)
        #pragma unroll
        for (int nt = 0; nt < 16; nt++) {
            int col = wn * 128 + nt * 8 + 2 * (lane & 3);
            float2 bb = *(float2*)(smf + F_B1 + col);
            float v0 = fmaxf(C[nt][0] + bb.x, 0.f), v1 = fmaxf(C[nt][1] + bb.y, 0.f);
            float v2 = fmaxf(C[nt][2] + bb.x, 0.f), v3 = fmaxf(C[nt][3] + bb.y, 0.f);
            uint32_t o0 = (uint32_t)r0 * AROW + (uint32_t)col * 2u;
            sts32(aP + o0, pack_h2(v0, v1));
            sts32(aP + o0 + 8 * AROW, pack_h2(v2, v3));
        }
    }

    // ---------------- GEMM2: h2 = relu(h1 @ w2 + b2), N=256, K=256 ----------------
    gemm_run<16>(C, 8, aP, bB, (uint32_t)wn * 128u * BROW, tid, lane, r0, t);
    __syncthreads();
    {   // ep2: bias+relu -> A plane; sigma partial per N-half
        float sl = 0.f, sh = 0.f;
        #pragma unroll
        for (int nt = 0; nt < 16; nt++) {
            int col = wn * 128 + nt * 8 + 2 * (lane & 3);
            float2 bb = *(float2*)(smf + F_B2 + col);
            float2 ws = *(float2*)(smf + F_WSIG + col);
            float v0 = fmaxf(C[nt][0] + bb.x, 0.f), v1 = fmaxf(C[nt][1] + bb.y, 0.f);
            float v2 = fmaxf(C[nt][2] + bb.x, 0.f), v3 = fmaxf(C[nt][3] + bb.y, 0.f);
            sl = fmaf(v0, ws.x, fmaf(v1, ws.y, sl));
            sh = fmaf(v2, ws.x, fmaf(v3, ws.y, sh));
            uint32_t o0 = (uint32_t)r0 * AROW + (uint32_t)col * 2u;
            sts32(aP + o0, pack_h2(v0, v1));
            sts32(aP + o0 + 8 * AROW, pack_h2(v2, v3));
        }
        sl = qred(sl); sh = qred(sh);
        if ((lane & 3) == 0) {
            smf[F_SIGP + wn * 64 + r0]     = sl;
            smf[F_SIGP + wn * 64 + r0 + 8] = sh;
        }
    }

    // ---------------- GEMM3: hd = relu(h2 @ w_dir_top + dc), N=128, K=256 ----------
    gemm_run<8>(C, 8, aP, bB, (uint32_t)wn * 64u * BROW, tid, lane, r0, t);
    __syncthreads();
    {   // ep3: rgb partial per N-half
        const float* dcp = smf + F_DC;
        float r0a = 0.f, g0a = 0.f, b0a = 0.f, r1a = 0.f, g1a = 0.f, b1a = 0.f;
        #pragma unroll
        for (int nt = 0; nt < 8; nt++) {
            int col = wn * 64 + nt * 8 + 2 * (lane & 3);
            float d0 = dcp[col], d1 = dcp[col + 1];
            float h0 = fmaxf(C[nt][0] + d0, 0.f), h1 = fmaxf(C[nt][1] + d1, 0.f);
            float h2 = fmaxf(C[nt][2] + d0, 0.f), h3 = fmaxf(C[nt][3] + d1, 0.f);
            const float* w0 = smf + F_WRGB + col * 3;
            const float* w1v = w0 + 3;
            r0a = fmaf(h0, w0[0], fmaf(h1, w1v[0], r0a));
            g0a = fmaf(h0, w0[1], fmaf(h1, w1v[1], g0a));
            b0a = fmaf(h0, w0[2], fmaf(h1, w1v[2], b0a));
            r1a = fmaf(h2, w0[0], fmaf(h3, w1v[0], r1a));
            g1a = fmaf(h2, w0[1], fmaf(h3, w1v[1], g1a));
            b1a = fmaf(h2, w0[2], fmaf(h3, w1v[2], b1a));
        }
        r0a = qred(r0a); g0a = qred(g0a); b0a = qred(b0a);
        r1a = qred(r1a); g1a = qred(g1a); b1a = qred(b1a);
        if ((lane & 3) == 0) {
            float* P = smf + F_RGBP + wn * 192;
            P[r0 * 3 + 0] = r0a; P[r0 * 3 + 1] = g0a; P[r0 * 3 + 2] = b0a;
            P[(r0 + 8) * 3 + 0] = r1a; P[(r0 + 8) * 3 + 1] = g1a; P[(r0 + 8) * 3 + 2] = b1a;
        }
    }
    __syncthreads();

    // final combine: sigmoid(rgb), alpha (exact sigma at the DINF sample)
    if (tid < 64) {
        int s = tid;
        float sg = smf[F_SIGP + s] + smf[F_SIGP + 64 + s] + bsigg[0];
        if (s == 63) sg = g_sig_last[ray];
        float nrm = smf[F_RAY + 9];
        smf[F_SIGP + s] = 1.0f - expf(-fmaxf(sg, 0.f) * g_dists[s] * nrm);
        #pragma unroll
        for (int c = 0; c < 3; c++) {
            float v = smf[F_RGBP + s * 3 + c] + smf[F_RGBP + 192 + s * 3 + c] + brgbg[c];
            smf[F_RGB + s * 3 + c] = 1.0f / (1.0f + expf(-v));
        }
    }
    __syncthreads();

    // compositing: cheap serial scan over precomputed alphas
    if (tid == 0) {
        float T = 1.0f, r = 0.0f, g = 0.0f, b = 0.0f;
        #pragma unroll 1
        for (int s = 0; s < NSAMP; s++) {
            float a = smf[F_SIGP + s];
            float w = a * T;
            r = fmaf(w, smf[F_RGB + s * 3 + 0], r);
            g = fmaf(w, smf[F_RGB + s * 3 + 1], g);
            b = fmaf(w, smf[F_RGB + s * 3 + 2], b);
            T *= (1.0f - a);
        }
        out[ray * 3 + 0] = r;
        out[ray * 3 + 1] = g;
        out[ray * 3 + 2] = b;
    }
}

extern "C" void kernel_launch(void* const* d_in, const int* in_sizes, int n_in,
                              void* d_out, int out_size) {
    const float* c2w    = (const float*)d_in[0];
    const float* t_rand = (const float*)d_in[1];
    const float* w1     = (const float*)d_in[2];
    const float* b1     = (const float*)d_in[3];
    const float* w2     = (const float*)d_in[4];
    const float* b2     = (const float*)d_in[5];
    const float* w_sig  = (const float*)d_in[6];
    const float* b_sig  = (const float*)d_in[7];
    const float* w_dir  = (const float*)d_in[8];
    const float* b_dir  = (const float*)d_in[9];
    const float* w_rgb  = (const float*)d_in[10];
    const float* b_rgb  = (const float*)d_in[11];
    float* out = (float*)d_out;

    cudaFuncSetAttribute(nerf_v3, cudaFuncAttributeMaxDynamicSharedMemorySize, SMEM_BYTES);

    precompute_kernel<<<1, NSAMP>>>(t_rand);
    prep_weights<<<448, 256>>>(w1, w2, w_dir);
    sigma_exact<<<625, 256>>>(c2w, w1, b1, w2, b2, w_sig, b_sig);
    nerf_v3<<<NBLOCKS, 256, SMEM_BYTES>>>(c2w, b1, b2, w_sig, b_sig,
                                          w_dir, b_dir, w_rgb, b_rgb, out);
}

// round 11
// speedup vs baseline: 1.2005x; 1.2005x over previous
#include <cuda_runtime.h>
#include <cuda_fp16.h>
#include <stdint.h>
#include <math.h>

#define NSAMP 64
#define NBLOCKS 5000           // 2 rays per block, M = 128 sample-rows
#define FXc 86.6f
#define NEAR_ 2.0f
#define FAR_ 6.0f
#define DINF 1e10f

// ---------------- global scratch (weights as fp16, [N][K]) ----------------
__device__ float g_z[NSAMP];
__device__ float g_dists[NSAMP];
__device__ float g_sig_last[10000];
__device__ __align__(16) __half g_w1T[256 * 64];
__device__ __align__(16) __half g_w2T[256 * 256];
__device__ __align__(16) __half g_wdT[128 * 256];

// ---------------- smem layout (bytes) ----------------
// [0, 16384)       misc floats
// [16384, 83968)   A plane: 128 rows x 264 fp16 (row stride 528 B)
// [83968, 194560)  B stages: 3 x 36864 B (256 rows x 72 fp16, 144 B stride)
#define A_OFF     16384u
#define B_OFF     83968u
#define STAGE_B   36864u
#define BROW      144u
#define AROW      528u
#define SMEM_BYTES 194560

// misc float offsets
#define F_RAY   0      // [2][12]
#define F_B1    32
#define F_B2    288
#define F_WSIG  544
#define F_WRGB  800    // 384
#define F_EDIR  1184   // [2][32]
#define F_DC    1248   // [2][128]
#define F_SIGP  1504   // [4][128] sigma partials; later alpha in [0..127]
#define F_RGB   2016   // [128][3]
#define F_RGBP  2400   // [4][384]

// ---------------- asm helpers ----------------
__device__ __forceinline__ uint32_t smem_u32(const void* p) {
    uint32_t a;
    asm("{ .reg .u64 t; cvta.to.shared.u64 t, %1; cvt.u32.u64 %0, t; }" : "=r"(a) : "l"(p));
    return a;
}
__device__ __forceinline__ void sts32(uint32_t a, uint32_t v) {
    asm volatile("st.shared.b32 [%0], %1;" :: "r"(a), "r"(v));
}
__device__ __forceinline__ void ldsm4(uint32_t* r, uint32_t addr) {
    asm volatile("ldmatrix.sync.aligned.m8n8.x4.shared.b16 {%0,%1,%2,%3}, [%4];"
        : "=r"(r[0]), "=r"(r[1]), "=r"(r[2]), "=r"(r[3]) : "r"(addr));
}
__device__ __forceinline__ void mma_f16(float* c, const uint32_t* a, uint32_t b0, uint32_t b1) {
    asm volatile(
        "mma.sync.aligned.m16n8k16.row.col.f32.f16.f16.f32 "
        "{%0,%1,%2,%3}, {%4,%5,%6,%7}, {%8,%9}, {%0,%1,%2,%3};"
        : "+f"(c[0]), "+f"(c[1]), "+f"(c[2]), "+f"(c[3])
        : "r"(a[0]), "r"(a[1]), "r"(a[2]), "r"(a[3]), "r"(b0), "r"(b1));
}
__device__ __forceinline__ void cpa16(uint32_t d, const void* s) {
    asm volatile("cp.async.ca.shared.global [%0], [%1], 16;" :: "r"(d), "l"(s));
}
#define CP_COMMIT() asm volatile("cp.async.commit_group;" ::: "memory")
#define CP_WAIT1()  asm volatile("cp.async.wait_group 1;" ::: "memory")

__device__ __forceinline__ uint32_t pack_h2(float a, float b) {
    __half2 h = __floats2half2_rn(a, b);
    return *reinterpret_cast<uint32_t*>(&h);
}
__device__ __forceinline__ float qred(float v) {
    v += __shfl_xor_sync(0xffffffffu, v, 1);
    v += __shfl_xor_sync(0xffffffffu, v, 2);
    return v;
}

// schedule: 9 items = G1 x1, G2 x4, G3 x4 (K=64 chunks)
__device__ __forceinline__ void fill_item(int t, uint32_t bB, int tid) {
    if (t >= 9) return;
    const __half* src; int nrows, kst, kb;
    if (t == 0)      { src = g_w1T; nrows = 256; kst = 64;  kb = 0; }
    else if (t < 5)  { src = g_w2T; nrows = 256; kst = 256; kb = (t - 1) * 64; }
    else             { src = g_wdT; nrows = 128; kst = 256; kb = (t - 5) * 64; }
    uint32_t dst = bB + (uint32_t)(t % 3) * STAGE_B;
    for (int i = tid; i < nrows * 8; i += 512) {
        int n = i >> 3, seg = i & 7;
        cpa16(dst + (uint32_t)n * BROW + (uint32_t)seg * 16u,
              src + n * kst + kb + seg * 8);
    }
}

// GEMM: M=128 via 4 M-warp-groups x 32 rows (2 m16 frags); 4 N-warp-groups x NT*8 cols.
// K=64 per chunk, 3-stage ring, ONE barrier per chunk. ldmatrix fragment loads.
template<int NT>   // N-tiles of 8 per warp: 8 (N=256) or 4 (N=128)
__device__ __forceinline__ void gemm_run(float (*C)[4], int nchunks,
                                         uint32_t aP, uint32_t bB,
                                         int wn, int wm, int lane, int tid, int& t) {
    // A ldmatrix lane addressing: row = wm*32 + f*16 + (lane&15), kel = 8*(lane>>4)
    const uint32_t aBase = aP + (uint32_t)(wm * 32 + (lane & 15)) * AROW
                         + ((uint32_t)(lane >> 4) << 4);
    // B ldmatrix: j=lane>>3: n = base + (lane&7) + 8*(j>>1), kel = 8*(j&1)
    const uint32_t bOff = (uint32_t)(wn * (NT * 8) + (lane & 7) + ((lane >> 4) << 3)) * BROW
                        + (((uint32_t)(lane >> 3) & 1u) << 4);
    #pragma unroll
    for (int i = 0; i < 2 * NT; i++) { C[i][0] = 0.f; C[i][1] = 0.f; C[i][2] = 0.f; C[i][3] = 0.f; }
    #pragma unroll 1
    for (int ch = 0; ch < nchunks; ch++) {
        CP_WAIT1();
        __syncthreads();
        uint32_t bs = bB + (uint32_t)(t % 3) * STAGE_B + bOff;
        #pragma unroll
        for (int k16 = 0; k16 < 4; k16++) {
            uint32_t kb = (uint32_t)(ch * 128 + k16 * 32);
            uint32_t a0[4], a1[4];
            ldsm4(a0, aBase + kb);
            ldsm4(a1, aBase + 16u * AROW + kb);
            uint32_t b[NT / 2][4];
            #pragma unroll
            for (int p = 0; p < NT / 2; p++)
                ldsm4(b[p], bs + (uint32_t)p * 16u * BROW + (uint32_t)(k16 * 32));
            #pragma unroll
            for (int p = 0; p < NT / 2; p++) {
                mma_f16(C[2 * p],          a0, b[p][0], b[p][1]);
                mma_f16(C[2 * p + 1],      a0, b[p][2], b[p][3]);
                mma_f16(C[NT + 2 * p],     a1, b[p][0], b[p][1]);
                mma_f16(C[NT + 2 * p + 1], a1, b[p][2], b[p][3]);
            }
        }
        fill_item(t + 2, bB, tid);
        CP_COMMIT();
        t++;
    }
}

// ---------------- aux kernels ----------------
__global__ void precompute_kernel(const float* __restrict__ t_rand) {
    __shared__ float zsh[NSAMP];
    int i = threadIdx.x;
    float t   = (float)i / 63.0f;
    float z0  = NEAR_ * (1.0f - t) + FAR_ * t;
    float tn  = (float)(i + 1) / 63.0f;
    float z0n = NEAR_ * (1.0f - tn) + FAR_ * tn;
    float tp  = (float)(i - 1) / 63.0f;
    float z0p = NEAR_ * (1.0f - tp) + FAR_ * tp;
    float upper = (i < NSAMP - 1) ? 0.5f * (z0 + z0n) : z0;
    float lower = (i > 0) ? 0.5f * (z0p + z0) : z0;
    float z = lower + (upper - lower) * t_rand[i];
    zsh[i] = z;
    g_z[i] = z;
    __syncthreads();
    g_dists[i] = (i < NSAMP - 1) ? (zsh[i + 1] - zsh[i]) : DINF;
}

__global__ void prep_weights(const float* __restrict__ w1,
                             const float* __restrict__ w2,
                             const float* __restrict__ wd) {
    int idx = blockIdx.x * 256 + threadIdx.x;
    if (idx < 16384) {
        int n = idx >> 6, k = idx & 63;
        g_w1T[idx] = __float2half((k < 63) ? w1[k * 256 + n] : 0.0f);
    } else if (idx < 16384 + 65536) {
        int t = idx - 16384; int n = t >> 8, k = t & 255;
        g_w2T[t] = __float2half(w2[k * 256 + n]);
    } else if (idx < 16384 + 65536 + 32768) {
        int t = idx - 16384 - 65536; int n = t >> 8, k = t & 255;
        g_wdT[t] = __float2half(wd[k * 128 + n]);
    }
}

// exact fp32 sigma for the LAST sample of each ray (alpha there is a step fn of sign(sigma))
__global__ void __launch_bounds__(256) sigma_exact(
    const float* __restrict__ c2w,
    const float* __restrict__ w1g, const float* __restrict__ b1g,
    const float* __restrict__ w2g, const float* __restrict__ b2g,
    const float* __restrict__ wsigg, const float* __restrict__ bsigg)
{
    __shared__ float enc[16][64];
    __shared__ float h1s[16][260];
    __shared__ float red[16][8];
    int tid = threadIdx.x;
    int r = tid >> 4, sub = tid & 15;
    {
        int ray = blockIdx.x * 16 + r;
        int cx = ray % 100, rw = ray / 100;
        float dx = ((float)cx - 50.0f) / FXc;
        float dy = -(((float)rw - 50.0f) / FXc);
        float d0 = dx * c2w[0] + dy * c2w[1] - c2w[2];
        float d1 = dx * c2w[4] + dy * c2w[5] - c2w[6];
        float d2 = dx * c2w[8] + dy * c2w[9] - c2w[10];
        float z = g_z[63];
        float pt[3];
        pt[0] = fmaf(d0, z, c2w[3]);
        pt[1] = fmaf(d1, z, c2w[7]);
        pt[2] = fmaf(d2, z, c2w[11]);
        #pragma unroll
        for (int q = 0; q < 4; q++) {
            int dd = sub * 4 + q;
            float val = 0.f;
            if (dd < 3) val = pt[dd];
            else if (dd < 63) {
                int u = dd - 3, l = u / 6, r6 = u % 6, cc = r6 % 3;
                float x = pt[cc] * (float)(1 << l);
                val = (r6 < 3) ? sinf(x) : cosf(x);
            }
            enc[r][dd] = val;
        }
    }
    __syncthreads();
    float acc[16];
    {
        float b = b1g[tid];
        #pragma unroll
        for (int i = 0; i < 16; i++) acc[i] = b;
        #pragma unroll 1
        for (int k = 0; k < 63; k++) {
            float w = w1g[k * 256 + tid];
            #pragma unroll
            for (int i = 0; i < 16; i++) acc[i] = fmaf(enc[i][k], w, acc[i]);
        }
        #pragma unroll
        for (int i = 0; i < 16; i++) h1s[i][tid] = fmaxf(acc[i], 0.f);
    }
    __syncthreads();
    {
        float b = b2g[tid];
        #pragma unroll
        for (int i = 0; i < 16; i++) acc[i] = b;
        #pragma unroll 1
        for (int k = 0; k < 256; k++) {
            float w = w2g[k * 256 + tid];
            #pragma unroll
            for (int i = 0; i < 16; i++) acc[i] = fmaf(h1s[i][k], w, acc[i]);
        }
    }
    {
        float ws = wsigg[tid];
        #pragma unroll
        for (int i = 0; i < 16; i++) {
            float v = fmaxf(acc[i], 0.f) * ws;
            v += __shfl_xor_sync(0xffffffffu, v, 16);
            v += __shfl_xor_sync(0xffffffffu, v, 8);
            v += __shfl_xor_sync(0xffffffffu, v, 4);
            v += __shfl_xor_sync(0xffffffffu, v, 2);
            v += __shfl_xor_sync(0xffffffffu, v, 1);
            if ((tid & 31) == 0) red[i][tid >> 5] = v;
        }
        __syncthreads();
        if (tid < 16) {
            float s = bsigg[0];
            #pragma unroll
            for (int w = 0; w < 8; w++) s += red[tid][w];
            g_sig_last[blockIdx.x * 16 + tid] = s;
        }
    }
}

// ---------------- main fused kernel (512 threads) ----------------
__global__ void __launch_bounds__(512, 1) nerf_v4(
    const float* __restrict__ c2w,
    const float* __restrict__ b1g,  const float* __restrict__ b2g,
    const float* __restrict__ wsigg,const float* __restrict__ bsigg,
    const float* __restrict__ wdirg,const float* __restrict__ bdirg,
    const float* __restrict__ wrgbg,const float* __restrict__ brgbg,
    float* __restrict__ out)
{
    extern __shared__ char smraw[];
    float* smf = (float*)smraw;
    const uint32_t base = smem_u32(smraw);
    const uint32_t aP = base + A_OFF, bB = base + B_OFF;
    const int tid = threadIdx.x, lane = tid & 31, wid = tid >> 5;
    const int wn = wid & 3, wm = wid >> 2;        // 4 N-quarters x 4 M-groups
    const int r0 = wm * 32 + (lane >> 2);         // rows r0, +8, +16, +24
    const int ray0 = blockIdx.x * 2;
    int t = 0;

    // prefetch first two chunk items
    fill_item(0, bB, tid); CP_COMMIT();
    fill_item(1, bB, tid); CP_COMMIT();

    // stage small tensors
    if (tid < 256) {
        smf[F_B1 + tid]   = b1g[tid];
        smf[F_B2 + tid]   = b2g[tid];
        smf[F_WSIG + tid] = wsigg[tid];
    }
    if (tid < 384) smf[F_WRGB + tid] = wrgbg[tid];
    if (tid < 2) {
        int ray = ray0 + tid;
        int c = ray % 100, rw = ray / 100;
        float dx = ((float)c - 50.0f) / FXc;
        float dy = -(((float)rw - 50.0f) / FXc);
        float d0 = dx * c2w[0] + dy * c2w[1] - c2w[2];
        float d1 = dx * c2w[4] + dy * c2w[5] - c2w[6];
        float d2 = dx * c2w[8] + dy * c2w[9] - c2w[10];
        float nrm = sqrtf(d0 * d0 + d1 * d1 + d2 * d2);
        float* R = smf + F_RAY + tid * 12;
        R[0] = c2w[3]; R[1] = c2w[7]; R[2] = c2w[11];
        R[3] = d0; R[4] = d1; R[5] = d2;
        R[6] = d0 / nrm; R[7] = d1 / nrm; R[8] = d2 / nrm;
        R[9] = nrm;
    }
    __syncthreads();

    // enc_dir (27 per ray) — precise (feeds fp32 dc path)
    if (tid < 54) {
        int rr = tid / 27, dd = tid - rr * 27;
        const float* vv = smf + F_RAY + rr * 12 + 6;
        float val;
        if (dd < 3) val = vv[dd];
        else {
            int u = dd - 3, l = u / 6, r6 = u % 6, cc = r6 % 3;
            float x = vv[cc] * (float)(1 << l);
            val = (r6 < 3) ? sinf(x) : cosf(x);
        }
        smf[F_EDIR + rr * 32 + dd] = val;
    }
    __syncthreads();

    // dir-head rank-1 bias dc[2][128] (fp32)
    if (tid < 256) {
        int j = tid & 127, rr = tid >> 7;
        float acc = bdirg[j];
        #pragma unroll
        for (int dd = 0; dd < 27; dd++)
            acc = fmaf(smf[F_EDIR + rr * 32 + dd], wdirg[(256 + dd) * 128 + j], acc);
        smf[F_DC + rr * 128 + j] = acc;
    }

    // posenc(pts) -> A plane fp16; fast sin/cos (error << fp16 rounding budget)
    if (tid < 128) {
        int rr = tid >> 6, s = tid & 63;
        float z = g_z[s];
        const float* R = smf + F_RAY + rr * 12;
        float v[64];
        float f0 = fmaf(R[3], z, R[0]);
        float f1 = fmaf(R[4], z, R[1]);
        float f2 = fmaf(R[5], z, R[2]);
        v[0] = f0; v[1] = f1; v[2] = f2;
        #pragma unroll
        for (int l = 0; l < 10; l++) {
            int b = 3 + l * 6;
            v[b]     = __sinf(f0); v[b + 1] = __sinf(f1); v[b + 2] = __sinf(f2);
            v[b + 3] = __cosf(f0); v[b + 4] = __cosf(f1); v[b + 5] = __cosf(f2);
            f0 *= 2.0f; f1 *= 2.0f; f2 *= 2.0f;
        }
        v[63] = 0.0f;
        uint32_t pk[32];
        #pragma unroll
        for (int i = 0; i < 32; i++) pk[i] = pack_h2(v[2 * i], v[2 * i + 1]);
        char* p = smraw + A_OFF + (uint32_t)tid * AROW;
        #pragma unroll
        for (int q = 0; q < 8; q++)
            *(uint4*)(p + q * 16) = ((uint4*)pk)[q];
    }
    // (gemm_run's first barrier orders A writes vs reads)

    float C[16][4];

    // ---------------- GEMM1: h1 = relu(enc @ w1 + b1), N=256, K=64 ----------------
    gemm_run<8>(C, 1, aP, bB, wn, wm, lane, tid, t);
    __syncthreads();
    {   // ep1: bias+relu -> A plane (fp16)
        #pragma unroll
        for (int f = 0; f < 2; f++)
            #pragma unroll
            for (int nt = 0; nt < 8; nt++) {
                int col = wn * 64 + nt * 8 + 2 * (lane & 3);
                int row = r0 + f * 16;
                float2 bb = *(float2*)(smf + F_B1 + col);
                float* c = C[f * 8 + nt];
                float v0 = fmaxf(c[0] + bb.x, 0.f), v1 = fmaxf(c[1] + bb.y, 0.f);
                float v2 = fmaxf(c[2] + bb.x, 0.f), v3 = fmaxf(c[3] + bb.y, 0.f);
                uint32_t o0 = (uint32_t)row * AROW + (uint32_t)col * 2u;
                sts32(aP + o0, pack_h2(v0, v1));
                sts32(aP + o0 + 8 * AROW, pack_h2(v2, v3));
            }
    }

    // ---------------- GEMM2: h2 = relu(h1 @ w2 + b2), N=256, K=256 ----------------
    gemm_run<8>(C, 4, aP, bB, wn, wm, lane, tid, t);
    __syncthreads();
    {   // ep2: bias+relu -> A plane; sigma partial per N-quarter
        float sp[4] = {0.f, 0.f, 0.f, 0.f};
        #pragma unroll
        for (int f = 0; f < 2; f++)
            #pragma unroll
            for (int nt = 0; nt < 8; nt++) {
                int col = wn * 64 + nt * 8 + 2 * (lane & 3);
                int row = r0 + f * 16;
                float2 bb = *(float2*)(smf + F_B2 + col);
                float2 ws = *(float2*)(smf + F_WSIG + col);
                float* c = C[f * 8 + nt];
                float v0 = fmaxf(c[0] + bb.x, 0.f), v1 = fmaxf(c[1] + bb.y, 0.f);
                float v2 = fmaxf(c[2] + bb.x, 0.f), v3 = fmaxf(c[3] + bb.y, 0.f);
                sp[f * 2]     = fmaf(v0, ws.x, fmaf(v1, ws.y, sp[f * 2]));
                sp[f * 2 + 1] = fmaf(v2, ws.x, fmaf(v3, ws.y, sp[f * 2 + 1]));
                uint32_t o0 = (uint32_t)row * AROW + (uint32_t)col * 2u;
                sts32(aP + o0, pack_h2(v0, v1));
                sts32(aP + o0 + 8 * AROW, pack_h2(v2, v3));
            }
        #pragma unroll
        for (int q = 0; q < 4; q++) sp[q] = qred(sp[q]);
        if ((lane & 3) == 0) {
            float* P = smf + F_SIGP + wn * 128;
            P[r0]      = sp[0];
            P[r0 + 8]  = sp[1];
            P[r0 + 16] = sp[2];
            P[r0 + 24] = sp[3];
        }
    }

    // ---------------- GEMM3: hd = relu(h2 @ w_dir_top + dc), N=128, K=256 ----------
    gemm_run<4>(C, 4, aP, bB, wn, wm, lane, tid, t);
    __syncthreads();
    {   // ep3: rgb partial per N-quarter
        int ray = wm >> 1;
        const float* dcp = smf + F_DC + ray * 128;
        float rp[4] = {0,0,0,0}, gp[4] = {0,0,0,0}, bp[4] = {0,0,0,0};
        #pragma unroll
        for (int f = 0; f < 2; f++)
            #pragma unroll
            for (int nt = 0; nt < 4; nt++) {
                int col = wn * 32 + nt * 8 + 2 * (lane & 3);
                float d0 = dcp[col], d1 = dcp[col + 1];
                float* c = C[f * 4 + nt];
                float h0 = fmaxf(c[0] + d0, 0.f), h1 = fmaxf(c[1] + d1, 0.f);
                float h2 = fmaxf(c[2] + d0, 0.f), h3 = fmaxf(c[3] + d1, 0.f);
                const float* w0 = smf + F_WRGB + col * 3;
                const float* w1v = w0 + 3;
                rp[f*2]   = fmaf(h0, w0[0], fmaf(h1, w1v[0], rp[f*2]));
                gp[f*2]   = fmaf(h0, w0[1], fmaf(h1, w1v[1], gp[f*2]));
                bp[f*2]   = fmaf(h0, w0[2], fmaf(h1, w1v[2], bp[f*2]));
                rp[f*2+1] = fmaf(h2, w0[0], fmaf(h3, w1v[0], rp[f*2+1]));
                gp[f*2+1] = fmaf(h2, w0[1], fmaf(h3, w1v[1], gp[f*2+1]));
                bp[f*2+1] = fmaf(h2, w0[2], fmaf(h3, w1v[2], bp[f*2+1]));
            }
        #pragma unroll
        for (int q = 0; q < 4; q++) { rp[q] = qred(rp[q]); gp[q] = qred(gp[q]); bp[q] = qred(bp[q]); }
        if ((lane & 3) == 0) {
            float* P = smf + F_RGBP + wn * 384;
            #pragma unroll
            for (int q = 0; q < 4; q++) {
                int row = r0 + q * 8;
                P[row * 3 + 0] = rp[q]; P[row * 3 + 1] = gp[q]; P[row * 3 + 2] = bp[q];
            }
        }
    }
    __syncthreads();

    // final combine: sigmoid(rgb), alpha (exact sigma at the DINF sample)
    if (tid < 128) {
        int row = tid, rr = row >> 6, s = row & 63;
        float sg = smf[F_SIGP + row] + smf[F_SIGP + 128 + row]
                 + smf[F_SIGP + 256 + row] + smf[F_SIGP + 384 + row] + bsigg[0];
        if (s == 63) sg = g_sig_last[ray0 + rr];
        float nrm = smf[F_RAY + rr * 12 + 9];
        smf[F_SIGP + row] = 1.0f - expf(-fmaxf(sg, 0.f) * g_dists[s] * nrm);
        #pragma unroll
        for (int c = 0; c < 3; c++) {
            float v = smf[F_RGBP + row * 3 + c] + smf[F_RGBP + 384 + row * 3 + c]
                    + smf[F_RGBP + 768 + row * 3 + c] + smf[F_RGBP + 1152 + row * 3 + c]
                    + brgbg[c];
            smf[F_RGB + row * 3 + c] = 1.0f / (1.0f + expf(-v));
        }
    }
    __syncthreads();

    // compositing: cheap serial scan over precomputed alphas
    if (tid < 2) {
        int ray = ray0 + tid;
        float T = 1.0f, r = 0.0f, g = 0.0f, b = 0.0f;
        #pragma unroll 1
        for (int s = 0; s < NSAMP; s++) {
            int m = tid * 64 + s;
            float a = smf[F_SIGP + m];
            float w = a * T;
            r = fmaf(w, smf[F_RGB + m * 3 + 0], r);
            g = fmaf(w, smf[F_RGB + m * 3 + 1], g);
            b = fmaf(w, smf[F_RGB + m * 3 + 2], b);
            T *= (1.0f - a);
        }
        out[ray * 3 + 0] = r;
        out[ray * 3 + 1] = g;
        out[ray * 3 + 2] = b;
    }
}

extern "C" void kernel_launch(void* const* d_in, const int* in_sizes, int n_in,
                              void* d_out, int out_size) {
    const float* c2w    = (const float*)d_in[0];
    const float* t_rand = (const float*)d_in[1];
    const float* w1     = (const float*)d_in[2];
    const float* b1     = (const float*)d_in[3];
    const float* w2     = (const float*)d_in[4];
    const float* b2     = (const float*)d_in[5];
    const float* w_sig  = (const float*)d_in[6];
    const float* b_sig  = (const float*)d_in[7];
    const float* w_dir  = (const float*)d_in[8];
    const float* b_dir  = (const float*)d_in[9];
    const float* w_rgb  = (const float*)d_in[10];
    const float* b_rgb  = (const float*)d_in[11];
    float* out = (float*)d_out;

    cudaFuncSetAttribute(nerf_v4, cudaFuncAttributeMaxDynamicSharedMemorySize, SMEM_BYTES);

    precompute_kernel<<<1, NSAMP>>>(t_rand);
    prep_weights<<<448, 256>>>(w1, w2, w_dir);
    sigma_exact<<<625, 256>>>(c2w, w1, b1, w2, b2, w_sig, b_sig);
    nerf_v4<<<NBLOCKS, 512, SMEM_BYTES>>>(c2w, b1, b2, w_sig, b_sig,
                                          w_dir, b_dir, w_rgb, b_rgb, out);
}

// round 12
// speedup vs baseline: 1.2769x; 1.0636x over previous
#include <cuda_runtime.h>
#include <cuda_fp16.h>
#include <stdint.h>
#include <math.h>

#define NSAMP 64
#define NBLOCKS 5000           // 2 rays per block, M = 128 sample-rows
#define FXc 86.6f
#define NEAR_ 2.0f
#define FAR_ 6.0f
#define DINF 1e10f

// ---------------- global scratch (weights as fp16, [N][K]) ----------------
__device__ float g_z[NSAMP];
__device__ float g_dists[NSAMP];
__device__ float g_sig_last[10000];
__device__ __align__(16) __half g_w1T[256 * 64];
__device__ __align__(16) __half g_w2T[256 * 256];
__device__ __align__(16) __half g_wdT[128 * 256];

// ---------------- smem layout (bytes) ----------------
#define A_OFF     16384u
#define B_OFF     83968u
#define STAGE_B   36864u
#define BROW      144u
#define AROW      528u
#define SMEM_BYTES 194560

// misc float offsets
#define F_RAY   0      // [2][12]
#define F_B1    32
#define F_B2    288
#define F_WSIG  544
#define F_WRGB  800    // 384
#define F_EDIR  1184   // [2][32]
#define F_DC    1248   // [2][128]
#define F_SIGP  1504   // [4][128]
#define F_RGB   2016   // [128][3]
#define F_RGBP  2400   // [4][384]

// ---------------- asm helpers ----------------
__device__ __forceinline__ uint32_t smem_u32(const void* p) {
    uint32_t a;
    asm("{ .reg .u64 t; cvta.to.shared.u64 t, %1; cvt.u32.u64 %0, t; }" : "=r"(a) : "l"(p));
    return a;
}
__device__ __forceinline__ void sts32(uint32_t a, uint32_t v) {
    asm volatile("st.shared.b32 [%0], %1;" :: "r"(a), "r"(v));
}
__device__ __forceinline__ void ldsm4(uint32_t* r, uint32_t addr) {
    asm volatile("ldmatrix.sync.aligned.m8n8.x4.shared.b16 {%0,%1,%2,%3}, [%4];"
        : "=r"(r[0]), "=r"(r[1]), "=r"(r[2]), "=r"(r[3]) : "r"(addr));
}
__device__ __forceinline__ void mma_f16(float* c, const uint32_t* a, uint32_t b0, uint32_t b1) {
    asm volatile(
        "mma.sync.aligned.m16n8k16.row.col.f32.f16.f16.f32 "
        "{%0,%1,%2,%3}, {%4,%5,%6,%7}, {%8,%9}, {%0,%1,%2,%3};"
        : "+f"(c[0]), "+f"(c[1]), "+f"(c[2]), "+f"(c[3])
        : "r"(a[0]), "r"(a[1]), "r"(a[2]), "r"(a[3]), "r"(b0), "r"(b1));
}
__device__ __forceinline__ void cpa16(uint32_t d, const void* s) {
    asm volatile("cp.async.ca.shared.global [%0], [%1], 16;" :: "r"(d), "l"(s));
}
#define CP_COMMIT() asm volatile("cp.async.commit_group;" ::: "memory")
#define CP_WAIT1()  asm volatile("cp.async.wait_group 1;" ::: "memory")

__device__ __forceinline__ uint32_t pack_h2(float a, float b) {
    __half2 h = __floats2half2_rn(a, b);
    return *reinterpret_cast<uint32_t*>(&h);
}
__device__ __forceinline__ float qred(float v) {
    v += __shfl_xor_sync(0xffffffffu, v, 1);
    v += __shfl_xor_sync(0xffffffffu, v, 2);
    return v;
}

// schedule: 9 items = G1 x1, G2 x4, G3 x4 (K=64 chunks)
__device__ __forceinline__ void fill_item(int t, uint32_t bB, int tid) {
    if (t >= 9) return;
    const __half* src; int nrows, kst, kb;
    if (t == 0)      { src = g_w1T; nrows = 256; kst = 64;  kb = 0; }
    else if (t < 5)  { src = g_w2T; nrows = 256; kst = 256; kb = (t - 1) * 64; }
    else             { src = g_wdT; nrows = 128; kst = 256; kb = (t - 5) * 64; }
    uint32_t dst = bB + (uint32_t)(t % 3) * STAGE_B;
    for (int i = tid; i < nrows * 8; i += 512) {
        int n = i >> 3, seg = i & 7;
        cpa16(dst + (uint32_t)n * BROW + (uint32_t)seg * 16u,
              src + n * kst + kb + seg * 8);
    }
}

// GEMM: 4 M-warp-groups x 32 rows; 4 N-warp-groups. K=64/chunk, 3-stage ring,
// one barrier per chunk; NEXT-NEXT chunk's cp.async issued BEFORE compute.
template<int NT>
__device__ __forceinline__ void gemm_run(float (*C)[4], int nchunks,
                                         uint32_t aP, uint32_t bB,
                                         int wn, int wm, int lane, int tid, int& t) {
    const uint32_t aBase = aP + (uint32_t)(wm * 32 + (lane & 15)) * AROW
                         + ((uint32_t)(lane >> 4) << 4);
    const uint32_t bOff = (uint32_t)(wn * (NT * 8) + (lane & 7) + ((lane >> 4) << 3)) * BROW
                        + (((uint32_t)(lane >> 3) & 1u) << 4);
    #pragma unroll
    for (int i = 0; i < 2 * NT; i++) { C[i][0] = 0.f; C[i][1] = 0.f; C[i][2] = 0.f; C[i][3] = 0.f; }
    #pragma unroll 1
    for (int ch = 0; ch < nchunks; ch++) {
        CP_WAIT1();
        __syncthreads();
        // prefetch t+2 into stage (t-1)%3 — its readers all passed this barrier
        fill_item(t + 2, bB, tid);
        CP_COMMIT();
        uint32_t bs = bB + (uint32_t)(t % 3) * STAGE_B + bOff;
        #pragma unroll
        for (int k16 = 0; k16 < 4; k16++) {
            uint32_t kb = (uint32_t)(ch * 128 + k16 * 32);
            uint32_t a0[4], a1[4];
            ldsm4(a0, aBase + kb);
            ldsm4(a1, aBase + 16u * AROW + kb);
            uint32_t b[NT / 2][4];
            #pragma unroll
            for (int p = 0; p < NT / 2; p++)
                ldsm4(b[p], bs + (uint32_t)p * 16u * BROW + (uint32_t)(k16 * 32));
            #pragma unroll
            for (int p = 0; p < NT / 2; p++) {
                mma_f16(C[2 * p],          a0, b[p][0], b[p][1]);
                mma_f16(C[2 * p + 1],      a0, b[p][2], b[p][3]);
                mma_f16(C[NT + 2 * p],     a1, b[p][0], b[p][1]);
                mma_f16(C[NT + 2 * p + 1], a1, b[p][2], b[p][3]);
            }
        }
        t++;
    }
}

// ---------------- aux kernels ----------------
__global__ void precompute_kernel(const float* __restrict__ t_rand) {
    __shared__ float zsh[NSAMP];
    int i = threadIdx.x;
    float t   = (float)i / 63.0f;
    float z0  = NEAR_ * (1.0f - t) + FAR_ * t;
    float tn  = (float)(i + 1) / 63.0f;
    float z0n = NEAR_ * (1.0f - tn) + FAR_ * tn;
    float tp  = (float)(i - 1) / 63.0f;
    float z0p = NEAR_ * (1.0f - tp) + FAR_ * tp;
    float upper = (i < NSAMP - 1) ? 0.5f * (z0 + z0n) : z0;
    float lower = (i > 0) ? 0.5f * (z0p + z0) : z0;
    float z = lower + (upper - lower) * t_rand[i];
    zsh[i] = z;
    g_z[i] = z;
    __syncthreads();
    g_dists[i] = (i < NSAMP - 1) ? (zsh[i + 1] - zsh[i]) : DINF;
}

// coalesced-read transpose+convert: block0 -> w1, block1 -> w2, block2 -> wd
__global__ void prep_weights(const float* __restrict__ w1,
                             const float* __restrict__ w2,
                             const float* __restrict__ wd) {
    int n = threadIdx.x;
    if (blockIdx.x == 0) {
        #pragma unroll 4
        for (int k = 0; k < 64; k++)
            g_w1T[n * 64 + k] = __float2half((k < 63) ? w1[k * 256 + n] : 0.0f);
    } else if (blockIdx.x == 1) {
        #pragma unroll 4
        for (int k = 0; k < 256; k++)
            g_w2T[n * 256 + k] = __float2half(w2[k * 256 + n]);
    } else if (n < 128) {
        #pragma unroll 4
        for (int k = 0; k < 256; k++)
            g_wdT[n * 256 + k] = __float2half(wd[k * 128 + n]);
    }
}

// exact fp32 sigma for the LAST sample of each ray (alpha there is a step fn of sign(sigma))
__global__ void __launch_bounds__(256) sigma_exact(
    const float* __restrict__ c2w,
    const float* __restrict__ w1g, const float* __restrict__ b1g,
    const float* __restrict__ w2g, const float* __restrict__ b2g,
    const float* __restrict__ wsigg, const float* __restrict__ bsigg)
{
    __shared__ float enc[16][64];
    __shared__ float h1s[16][260];
    __shared__ float red[16][8];
    int tid = threadIdx.x;
    int r = tid >> 4, sub = tid & 15;
    {
        int ray = blockIdx.x * 16 + r;
        int cx = ray % 100, rw = ray / 100;
        float dx = ((float)cx - 50.0f) / FXc;
        float dy = -(((float)rw - 50.0f) / FXc);
        float d0 = dx * c2w[0] + dy * c2w[1] - c2w[2];
        float d1 = dx * c2w[4] + dy * c2w[5] - c2w[6];
        float d2 = dx * c2w[8] + dy * c2w[9] - c2w[10];
        float z = g_z[63];
        float pt[3];
        pt[0] = fmaf(d0, z, c2w[3]);
        pt[1] = fmaf(d1, z, c2w[7]);
        pt[2] = fmaf(d2, z, c2w[11]);
        #pragma unroll
        for (int q = 0; q < 4; q++) {
            int dd = sub * 4 + q;
            float val = 0.f;
            if (dd < 3) val = pt[dd];
            else if (dd < 63) {
                int u = dd - 3, l = u / 6, r6 = u % 6, cc = r6 % 3;
                float x = pt[cc] * (float)(1 << l);
                val = (r6 < 3) ? sinf(x) : cosf(x);
            }
            enc[r][dd] = val;
        }
    }
    __syncthreads();
    float acc[16];
    {
        float b = b1g[tid];
        #pragma unroll
        for (int i = 0; i < 16; i++) acc[i] = b;
        int k = 0;
        #pragma unroll 1
        for (; k + 3 < 63; k += 4) {
            float wa = w1g[k * 256 + tid];
            float wb = w1g[(k + 1) * 256 + tid];
            float wc = w1g[(k + 2) * 256 + tid];
            float wdv = w1g[(k + 3) * 256 + tid];
            #pragma unroll
            for (int i = 0; i < 16; i++)
                acc[i] = fmaf(enc[i][k], wa,
                         fmaf(enc[i][k + 1], wb,
                         fmaf(enc[i][k + 2], wc,
                         fmaf(enc[i][k + 3], wdv, acc[i]))));
        }
        #pragma unroll
        for (; k < 63; k++) {
            float w = w1g[k * 256 + tid];
            #pragma unroll
            for (int i = 0; i < 16; i++) acc[i] = fmaf(enc[i][k], w, acc[i]);
        }
        #pragma unroll
        for (int i = 0; i < 16; i++) h1s[i][tid] = fmaxf(acc[i], 0.f);
    }
    __syncthreads();
    {
        float b = b2g[tid];
        #pragma unroll
        for (int i = 0; i < 16; i++) acc[i] = b;
        #pragma unroll 1
        for (int k = 0; k < 256; k += 4) {
            float wa = w2g[k * 256 + tid];
            float wb = w2g[(k + 1) * 256 + tid];
            float wc = w2g[(k + 2) * 256 + tid];
            float wdv = w2g[(k + 3) * 256 + tid];
            #pragma unroll
            for (int i = 0; i < 16; i++)
                acc[i] = fmaf(h1s[i][k], wa,
                         fmaf(h1s[i][k + 1], wb,
                         fmaf(h1s[i][k + 2], wc,
                         fmaf(h1s[i][k + 3], wdv, acc[i]))));
        }
    }
    {
        float ws = wsigg[tid];
        #pragma unroll
        for (int i = 0; i < 16; i++) {
            float v = fmaxf(acc[i], 0.f) * ws;
            v += __shfl_xor_sync(0xffffffffu, v, 16);
            v += __shfl_xor_sync(0xffffffffu, v, 8);
            v += __shfl_xor_sync(0xffffffffu, v, 4);
            v += __shfl_xor_sync(0xffffffffu, v, 2);
            v += __shfl_xor_sync(0xffffffffu, v, 1);
            if ((tid & 31) == 0) red[i][tid >> 5] = v;
        }
        __syncthreads();
        if (tid < 16) {
            float s = bsigg[0];
            #pragma unroll
            for (int w = 0; w < 8; w++) s += red[tid][w];
            g_sig_last[blockIdx.x * 16 + tid] = s;
        }
    }
}

// ---------------- main fused kernel (512 threads) ----------------
__global__ void __launch_bounds__(512, 1) nerf_v5(
    const float* __restrict__ c2w,
    const float* __restrict__ b1g,  const float* __restrict__ b2g,
    const float* __restrict__ wsigg,const float* __restrict__ bsigg,
    const float* __restrict__ wdirg,const float* __restrict__ bdirg,
    const float* __restrict__ wrgbg,const float* __restrict__ brgbg,
    float* __restrict__ out)
{
    extern __shared__ char smraw[];
    float* smf = (float*)smraw;
    const uint32_t base = smem_u32(smraw);
    const uint32_t aP = base + A_OFF, bB = base + B_OFF;
    const int tid = threadIdx.x, lane = tid & 31, wid = tid >> 5;
    const int wn = wid & 3, wm = wid >> 2;
    const int r0 = wm * 32 + (lane >> 2);
    const int ray0 = blockIdx.x * 2;
    int t = 0;

    fill_item(0, bB, tid); CP_COMMIT();
    fill_item(1, bB, tid); CP_COMMIT();

    if (tid < 256) {
        smf[F_B1 + tid]   = b1g[tid];
        smf[F_B2 + tid]   = b2g[tid];
        smf[F_WSIG + tid] = wsigg[tid];
    }
    if (tid < 384) smf[F_WRGB + tid] = wrgbg[tid];
    if (tid < 2) {
        int ray = ray0 + tid;
        int c = ray % 100, rw = ray / 100;
        float dx = ((float)c - 50.0f) / FXc;
        float dy = -(((float)rw - 50.0f) / FXc);
        float d0 = dx * c2w[0] + dy * c2w[1] - c2w[2];
        float d1 = dx * c2w[4] + dy * c2w[5] - c2w[6];
        float d2 = dx * c2w[8] + dy * c2w[9] - c2w[10];
        float nrm = sqrtf(d0 * d0 + d1 * d1 + d2 * d2);
        float* R = smf + F_RAY + tid * 12;
        R[0] = c2w[3]; R[1] = c2w[7]; R[2] = c2w[11];
        R[3] = d0; R[4] = d1; R[5] = d2;
        R[6] = d0 / nrm; R[7] = d1 / nrm; R[8] = d2 / nrm;
        R[9] = nrm;
    }
    __syncthreads();

    if (tid < 54) {
        int rr = tid / 27, dd = tid - rr * 27;
        const float* vv = smf + F_RAY + rr * 12 + 6;
        float val;
        if (dd < 3) val = vv[dd];
        else {
            int u = dd - 3, l = u / 6, r6 = u % 6, cc = r6 % 3;
            float x = vv[cc] * (float)(1 << l);
            val = (r6 < 3) ? sinf(x) : cosf(x);
        }
        smf[F_EDIR + rr * 32 + dd] = val;
    }
    __syncthreads();

    if (tid < 256) {
        int j = tid & 127, rr = tid >> 7;
        float acc = bdirg[j];
        #pragma unroll
        for (int dd = 0; dd < 27; dd++)
            acc = fmaf(smf[F_EDIR + rr * 32 + dd], wdirg[(256 + dd) * 128 + j], acc);
        smf[F_DC + rr * 128 + j] = acc;
    }

    if (tid < 128) {
        int rr = tid >> 6, s = tid & 63;
        float z = g_z[s];
        const float* R = smf + F_RAY + rr * 12;
        float v[64];
        float f0 = fmaf(R[3], z, R[0]);
        float f1 = fmaf(R[4], z, R[1]);
        float f2 = fmaf(R[5], z, R[2]);
        v[0] = f0; v[1] = f1; v[2] = f2;
        #pragma unroll
        for (int l = 0; l < 10; l++) {
            int b = 3 + l * 6;
            v[b]     = __sinf(f0); v[b + 1] = __sinf(f1); v[b + 2] = __sinf(f2);
            v[b + 3] = __cosf(f0); v[b + 4] = __cosf(f1); v[b + 5] = __cosf(f2);
            f0 *= 2.0f; f1 *= 2.0f; f2 *= 2.0f;
        }
        v[63] = 0.0f;
        uint32_t pk[32];
        #pragma unroll
        for (int i = 0; i < 32; i++) pk[i] = pack_h2(v[2 * i], v[2 * i + 1]);
        char* p = smraw + A_OFF + (uint32_t)tid * AROW;
        #pragma unroll
        for (int q = 0; q < 8; q++)
            *(uint4*)(p + q * 16) = ((uint4*)pk)[q];
    }

    float C[16][4];

    // ---------------- GEMM1: h1 = relu(enc @ w1 + b1), N=256, K=64 ----------------
    gemm_run<8>(C, 1, aP, bB, wn, wm, lane, tid, t);
    __syncthreads();
    {
        #pragma unroll
        for (int f = 0; f < 2; f++)
            #pragma unroll
            for (int nt = 0; nt < 8; nt++) {
                int col = wn * 64 + nt * 8 + 2 * (lane & 3);
                int row = r0 + f * 16;
                float2 bb = *(float2*)(smf + F_B1 + col);
                float* c = C[f * 8 + nt];
                float v0 = fmaxf(c[0] + bb.x, 0.f), v1 = fmaxf(c[1] + bb.y, 0.f);
                float v2 = fmaxf(c[2] + bb.x, 0.f), v3 = fmaxf(c[3] + bb.y, 0.f);
                uint32_t o0 = (uint32_t)row * AROW + (uint32_t)col * 2u;
                sts32(aP + o0, pack_h2(v0, v1));
                sts32(aP + o0 + 8 * AROW, pack_h2(v2, v3));
            }
    }

    // ---------------- GEMM2: h2 = relu(h1 @ w2 + b2), N=256, K=256 ----------------
    gemm_run<8>(C, 4, aP, bB, wn, wm, lane, tid, t);
    __syncthreads();
    {
        float sp[4] = {0.f, 0.f, 0.f, 0.f};
        #pragma unroll
        for (int f = 0; f < 2; f++)
            #pragma unroll
            for (int nt = 0; nt < 8; nt++) {
                int col = wn * 64 + nt * 8 + 2 * (lane & 3);
                int row = r0 + f * 16;
                float2 bb = *(float2*)(smf + F_B2 + col);
                float2 ws = *(float2*)(smf + F_WSIG + col);
                float* c = C[f * 8 + nt];
                float v0 = fmaxf(c[0] + bb.x, 0.f), v1 = fmaxf(c[1] + bb.y, 0.f);
                float v2 = fmaxf(c[2] + bb.x, 0.f), v3 = fmaxf(c[3] + bb.y, 0.f);
                sp[f * 2]     = fmaf(v0, ws.x, fmaf(v1, ws.y, sp[f * 2]));
                sp[f * 2 + 1] = fmaf(v2, ws.x, fmaf(v3, ws.y, sp[f * 2 + 1]));
                uint32_t o0 = (uint32_t)row * AROW + (uint32_t)col * 2u;
                sts32(aP + o0, pack_h2(v0, v1));
                sts32(aP + o0 + 8 * AROW, pack_h2(v2, v3));
            }
        #pragma unroll
        for (int q = 0; q < 4; q++) sp[q] = qred(sp[q]);
        if ((lane & 3) == 0) {
            float* P = smf + F_SIGP + wn * 128;
            P[r0]      = sp[0];
            P[r0 + 8]  = sp[1];
            P[r0 + 16] = sp[2];
            P[r0 + 24] = sp[3];
        }
    }

    // ---------------- GEMM3: hd = relu(h2 @ w_dir_top + dc), N=128, K=256 ----------
    gemm_run<4>(C, 4, aP, bB, wn, wm, lane, tid, t);
    __syncthreads();
    {
        int ray = wm >> 1;
        const float* dcp = smf + F_DC + ray * 128;
        float rp[4] = {0,0,0,0}, gp[4] = {0,0,0,0}, bp[4] = {0,0,0,0};
        #pragma unroll
        for (int f = 0; f < 2; f++)
            #pragma unroll
            for (int nt = 0; nt < 4; nt++) {
                int col = wn * 32 + nt * 8 + 2 * (lane & 3);
                float d0 = dcp[col], d1 = dcp[col + 1];
                float* c = C[f * 4 + nt];
                float h0 = fmaxf(c[0] + d0, 0.f), h1 = fmaxf(c[1] + d1, 0.f);
                float h2 = fmaxf(c[2] + d0, 0.f), h3 = fmaxf(c[3] + d1, 0.f);
                const float* w0 = smf + F_WRGB + col * 3;
                const float* w1v = w0 + 3;
                rp[f*2]   = fmaf(h0, w0[0], fmaf(h1, w1v[0], rp[f*2]));
                gp[f*2]   = fmaf(h0, w0[1], fmaf(h1, w1v[1], gp[f*2]));
                bp[f*2]   = fmaf(h0, w0[2], fmaf(h1, w1v[2], bp[f*2]));
                rp[f*2+1] = fmaf(h2, w0[0], fmaf(h3, w1v[0], rp[f*2+1]));
                gp[f*2+1] = fmaf(h2, w0[1], fmaf(h3, w1v[1], gp[f*2+1]));
                bp[f*2+1] = fmaf(h2, w0[2], fmaf(h3, w1v[2], bp[f*2+1]));
            }
        #pragma unroll
        for (int q = 0; q < 4; q++) { rp[q] = qred(rp[q]); gp[q] = qred(gp[q]); bp[q] = qred(bp[q]); }
        if ((lane & 3) == 0) {
            float* P = smf + F_RGBP + wn * 384;
            #pragma unroll
            for (int q = 0; q < 4; q++) {
                int row = r0 + q * 8;
                P[row * 3 + 0] = rp[q]; P[row * 3 + 1] = gp[q]; P[row * 3 + 2] = bp[q];
            }
        }
    }
    __syncthreads();

    if (tid < 128) {
        int row = tid, rr = row >> 6, s = row & 63;
        float sg = smf[F_SIGP + row] + smf[F_SIGP + 128 + row]
                 + smf[F_SIGP + 256 + row] + smf[F_SIGP + 384 + row] + bsigg[0];
        if (s == 63) sg = g_sig_last[ray0 + rr];
        float nrm = smf[F_RAY + rr * 12 + 9];
        smf[F_SIGP + row] = 1.0f - expf(-fmaxf(sg, 0.f) * g_dists[s] * nrm);
        #pragma unroll
        for (int c = 0; c < 3; c++) {
            float v = smf[F_RGBP + row * 3 + c] + smf[F_RGBP + 384 + row * 3 + c]
                    + smf[F_RGBP + 768 + row * 3 + c] + smf[F_RGBP + 1152 + row * 3 + c]
                    + brgbg[c];
            smf[F_RGB + row * 3 + c] = 1.0f / (1.0f + expf(-v));
        }
    }
    __syncthreads();

    if (tid < 2) {
        int ray = ray0 + tid;
        float T = 1.0f, r = 0.0f, g = 0.0f, b = 0.0f;
        #pragma unroll 1
        for (int s = 0; s < NSAMP; s++) {
            int m = tid * 64 + s;
            float a = smf[F_SIGP + m];
            float w = a * T;
            r = fmaf(w, smf[F_RGB + m * 3 + 0], r);
            g = fmaf(w, smf[F_RGB + m * 3 + 1], g);
            b = fmaf(w, smf[F_RGB + m * 3 + 2], b);
            T *= (1.0f - a);
        }
        out[ray * 3 + 0] = r;
        out[ray * 3 + 1] = g;
        out[ray * 3 + 2] = b;
    }
}

extern "C" void kernel_launch(void* const* d_in, const int* in_sizes, int n_in,
                              void* d_out, int out_size) {
    const float* c2w    = (const float*)d_in[0];
    const float* t_rand = (const float*)d_in[1];
    const float* w1     = (const float*)d_in[2];
    const float* b1     = (const float*)d_in[3];
    const float* w2     = (const float*)d_in[4];
    const float* b2     = (const float*)d_in[5];
    const float* w_sig  = (const float*)d_in[6];
    const float* b_sig  = (const float*)d_in[7];
    const float* w_dir  = (const float*)d_in[8];
    const float* b_dir  = (const float*)d_in[9];
    const float* w_rgb  = (const float*)d_in[10];
    const float* b_rgb  = (const float*)d_in[11];
    float* out = (float*)d_out;

    cudaFuncSetAttribute(nerf_v5, cudaFuncAttributeMaxDynamicSharedMemorySize, SMEM_BYTES);

    precompute_kernel<<<1, NSAMP>>>(t_rand);
    prep_weights<<<3, 256>>>(w1, w2, w_dir);
    sigma_exact<<<625, 256>>>(c2w, w1, b1, w2, b2, w_sig, b_sig);
    nerf_v5<<<NBLOCKS, 512, SMEM_BYTES>>>(c2w, b1, b2, w_sig, b_sig,
                                          w_dir, b_dir, w_rgb, b_rgb, out);
}